// round 7
// baseline (speedup 1.0000x reference)
#include <cuda_runtime.h>
#include <cstdint>

// ---------------------------------------------------------------------------
// out = sx*sy * ( X@Y - zpy*rowsum(X)[m] - zpx*colsum(Y)[n] + K*zpx*zpy )
// Inputs arrive as INT32 (harness canonical dtype), values in [-128,127].
//   d_in[0]: X [4096,4096] int32  -> packed to int8 g_xp [M,K]
//   d_in[1]: Y [4096,4096] int32  -> packed+transposed to int8 g_yt [N,K]
// S computed exactly in s32 via mma.sync m16n8k32 (IMMA), fragments via
// plain ld.shared per the PTX fragment tables.
// ---------------------------------------------------------------------------

static constexpr int MD = 4096, KD = 4096, ND = 4096;
static constexpr float KZZf = -1843200.0f;     // K*zpx*zpy = 4096*(-25)*18
static constexpr float SXY  = 0.0215f * 0.0176f;

__device__ int8_t g_xp[(size_t)MD * KD];       // 16MB packed X
__device__ int8_t g_yt[(size_t)ND * KD];       // 16MB packed transposed Y
__device__ float  g_rxf[MD];                   // -18 * rowsum_x[m]
__device__ float  g_cyf[ND];                   // +25 * colsum_y[n] + KZZ

// ------------------------------ helpers -----------------------------------

__device__ __forceinline__ uint32_t smem_u32(const void* p) {
    uint32_t a;
    asm("{ .reg .u64 t; cvta.to.shared.u64 t, %1; cvt.u32.u64 %0, t; }"
        : "=r"(a) : "l"(p));
    return a;
}

__device__ __forceinline__ void cp16(uint32_t dst, const void* src) {
    asm volatile("cp.async.cg.shared.global [%0], [%1], 16;" :: "r"(dst), "l"(src));
}
#define CP_COMMIT() asm volatile("cp.async.commit_group;" ::: "memory")

__device__ __forceinline__ uint32_t lds32(uint32_t addr) {
    uint32_t v;
    asm volatile("ld.shared.b32 %0, [%1];" : "=r"(v) : "r"(addr));
    return v;
}

#define MMA_S8(d, a0, a1, a2, a3, b0, b1) \
    asm volatile("mma.sync.aligned.m16n8k32.row.col.s32.s8.s8.s32 " \
                 "{%0,%1,%2,%3},{%4,%5,%6,%7},{%8,%9},{%0,%1,%2,%3};" \
                 : "+r"((d)[0]), "+r"((d)[1]), "+r"((d)[2]), "+r"((d)[3]) \
                 : "r"(a0), "r"(a1), "r"(a2), "r"(a3), "r"(b0), "r"(b1))

// smem tile layout: 128 rows x 64B, XOR-swizzled over 128B lines (8x16B slots)
__device__ __forceinline__ uint32_t sw_off(int r, int c) {
    int line = r >> 1;
    int slot = (((r & 1) * 4 + c) ^ (line & 7));
    return (uint32_t)(line * 128 + slot * 16);
}

// ------------------------------ prepasses ---------------------------------

// int32 -> int8 pack of X
__global__ void k_pack_x(const int4* __restrict__ q) {
    size_t i = (size_t)blockIdx.x * 256 + threadIdx.x;   // group of 4 elems
    int4 v = q[i];
    char4 c;
    c.x = (char)v.x; c.y = (char)v.y; c.z = (char)v.z; c.w = (char)v.w;
    ((char4*)g_xp)[i] = c;
}

// Y int32 [K,N] -> g_yt int8 [N,K], 32x32 tiles
__global__ void k_pack_transpose_y(const int* __restrict__ Y) {
    __shared__ int8_t tile[32][36];
    int n0 = blockIdx.x * 32, k0 = blockIdx.y * 32;
    int t = threadIdx.x;
    {
        int k = t >> 3, nq = (t & 7) * 4;
        int4 v = *(const int4*)(Y + (size_t)(k0 + k) * ND + n0 + nq);
        tile[nq + 0][k] = (int8_t)v.x;
        tile[nq + 1][k] = (int8_t)v.y;
        tile[nq + 2][k] = (int8_t)v.z;
        tile[nq + 3][k] = (int8_t)v.w;
    }
    __syncthreads();
    {
        int n = t >> 3, kq = (t & 7) * 4;
        char4 c;
        c.x = tile[n][kq + 0]; c.y = tile[n][kq + 1];
        c.z = tile[n][kq + 2]; c.w = tile[n][kq + 3];
        *(char4*)(g_yt + (size_t)(n0 + n) * KD + k0 + kq) = c;
    }
}

// rowsum of packed X -> g_rxf[m] = -18 * rowsum
__global__ void k_rowsum(void) {
    const unsigned* xw = (const unsigned*)g_xp;
    int m = blockIdx.x, t = threadIdx.x;     // 128 threads, 1024 words/row
    int acc = 0;
#pragma unroll
    for (int j = 0; j < 8; j++)
        acc = __dp4a((int)xw[(size_t)m * 1024 + t + 128 * j], 0x01010101, acc);
#pragma unroll
    for (int s = 16; s; s >>= 1) acc += __shfl_xor_sync(0xffffffffu, acc, s);
    __shared__ int ws[4];
    if ((t & 31) == 0) ws[t >> 5] = acc;
    __syncthreads();
    if (t == 0) g_rxf[m] = -18.0f * (float)(ws[0] + ws[1] + ws[2] + ws[3]);
}

// colsum of Y = rowsum of g_yt -> g_cyf[n] = 25 * colsum + KZZ
__global__ void k_colsum(void) {
    const unsigned* yw = (const unsigned*)g_yt;
    int n = blockIdx.x, t = threadIdx.x;
    int acc = 0;
#pragma unroll
    for (int j = 0; j < 8; j++)
        acc = __dp4a((int)yw[(size_t)n * 1024 + t + 128 * j], 0x01010101, acc);
#pragma unroll
    for (int s = 16; s; s >>= 1) acc += __shfl_xor_sync(0xffffffffu, acc, s);
    __shared__ int ws[4];
    if ((t & 31) == 0) ws[t >> 5] = acc;
    __syncthreads();
    if (t == 0) g_cyf[n] = 25.0f * (float)(ws[0] + ws[1] + ws[2] + ws[3]) + KZZf;
}

// ------------------------------- GEMM -------------------------------------
// CTA tile 128(M)x128(N), K-stage 64, 4-stage cp.async.
// 256 threads = 8 warps (4 M x 2 N), warp tile 32x64.

static constexpr int STAGES = 4;
static constexpr int STAGE_BYTES = 16384;
static constexpr int SMEM_TOTAL = STAGES * STAGE_BYTES;   // 65536
static constexpr int KITERS = KD / 64;                    // 64

__device__ __forceinline__ void load_tile(uint32_t sbase, int stage, int kt,
                                          int m0, int n0) {
    const int t = threadIdx.x;
    const uint32_t sA = sbase + stage * STAGE_BYTES;
    const uint32_t sB = sA + 8192;
    const int kb = kt * 64;
#pragma unroll
    for (int j = 0; j < 2; j++) {
        int idx = t + 256 * j;              // 0..511
        int r = idx >> 2, c = idx & 3;
        cp16(sA + sw_off(r, c), g_xp + (size_t)(m0 + r) * KD + kb + c * 16);
        cp16(sB + sw_off(r, c), g_yt + (size_t)(n0 + r) * KD + kb + c * 16);
    }
}

__global__ void __launch_bounds__(256)
gemm_i8_kernel(float* __restrict__ OUT) {
    extern __shared__ char smem[];
    const uint32_t sbase = smem_u32(smem);
    const int tid = threadIdx.x;
    const int lane = tid & 31;
    const int wid = tid >> 5;
    const int wm = wid & 3;                 // 0..3  (M quadrant, 32 rows)
    const int wn = wid >> 2;                // 0..1  (N half, 64 cols)
    const int m0 = blockIdx.y * 128;
    const int n0 = blockIdx.x * 128;

    const int gid = lane >> 2;              // groupID (0..7)
    const int tig = lane & 3;               // threadID_in_group (0..3)

    int acc[2][8][4];
#pragma unroll
    for (int i = 0; i < 2; i++)
#pragma unroll
        for (int j = 0; j < 8; j++)
#pragma unroll
            for (int q = 0; q < 4; q++) acc[i][j][q] = 0;

    // prologue: 3 stages in flight
#pragma unroll
    for (int p = 0; p < 3; p++) { load_tile(sbase, p, p, m0, n0); CP_COMMIT(); }

    for (int it = 0; it < KITERS; it++) {
        asm volatile("cp.async.wait_group 2;" ::: "memory");
        __syncthreads();

        if (it + 3 < KITERS) load_tile(sbase, (it + 3) & 3, it + 3, m0, n0);
        CP_COMMIT();

        const uint32_t sA = sbase + (it & 3) * STAGE_BYTES;
        const uint32_t sB = sA + 8192;

#pragma unroll
        for (int ks = 0; ks < 2; ks++) {
            // A fragments per PTX table:
            // a0:(gid, k.lo) a1:(gid+8, k.lo) a2:(gid, k.hi) a3:(gid+8, k.hi)
            uint32_t a[2][4];
#pragma unroll
            for (int mt = 0; mt < 2; mt++) {
                const int rb = wm * 32 + mt * 16 + gid;
                a[mt][0] = lds32(sA + sw_off(rb,     2 * ks)     + tig * 4);
                a[mt][1] = lds32(sA + sw_off(rb + 8, 2 * ks)     + tig * 4);
                a[mt][2] = lds32(sA + sw_off(rb,     2 * ks + 1) + tig * 4);
                a[mt][3] = lds32(sA + sw_off(rb + 8, 2 * ks + 1) + tig * 4);
            }
            // B fragments: b0:(n=gid, k.lo) b1:(n=gid, k.hi)
#pragma unroll
            for (int nt = 0; nt < 8; nt++) {
                const int nb = wn * 64 + nt * 8 + gid;
                uint32_t b0 = lds32(sB + sw_off(nb, 2 * ks)     + tig * 4);
                uint32_t b1 = lds32(sB + sw_off(nb, 2 * ks + 1) + tig * 4);
                MMA_S8(acc[0][nt], a[0][0], a[0][1], a[0][2], a[0][3], b0, b1);
                MMA_S8(acc[1][nt], a[1][0], a[1][1], a[1][2], a[1][3], b0, b1);
            }
        }
    }

    __syncthreads();

    // stage per-column correction into smem
    float* scy = (float*)smem;
    if (tid < 128) scy[tid] = g_cyf[n0 + tid];
    __syncthreads();

#pragma unroll
    for (int mt = 0; mt < 2; mt++) {
#pragma unroll
        for (int h = 0; h < 2; h++) {
            const int rloc = wm * 32 + mt * 16 + h * 8 + gid;
            const float rf = g_rxf[m0 + rloc];
            float* orow = OUT + (size_t)(m0 + rloc) * ND + n0 + wn * 64 + tig * 2;
#pragma unroll
            for (int nt = 0; nt < 8; nt++) {
                const int cidx = wn * 64 + nt * 8 + tig * 2;
                float2 v;
                v.x = SXY * ((float)acc[mt][nt][h * 2 + 0] + rf + scy[cidx + 0]);
                v.y = SXY * ((float)acc[mt][nt][h * 2 + 1] + rf + scy[cidx + 1]);
                *(float2*)(orow + nt * 8) = v;
            }
        }
    }
}

// ------------------------------- launch ------------------------------------

extern "C" void kernel_launch(void* const* d_in, const int* in_sizes, int n_in,
                              void* d_out, int out_size) {
    const int* X32 = (const int*)d_in[0];
    const int* Y32 = (const int*)d_in[1];
    float* OUT = (float*)d_out;

    cudaFuncSetAttribute(gemm_i8_kernel,
                         cudaFuncAttributeMaxDynamicSharedMemorySize, SMEM_TOTAL);

    k_pack_x<<<16384, 256>>>((const int4*)X32);
    k_pack_transpose_y<<<dim3(ND / 32, KD / 32), 256>>>(Y32);
    k_rowsum<<<MD, 128>>>();
    k_colsum<<<ND, 128>>>();
    gemm_i8_kernel<<<dim3(ND / 128, MD / 128), 256, SMEM_TOTAL>>>(OUT);
}

// round 8
// speedup vs baseline: 1.0658x; 1.0658x over previous
#include <cuda_runtime.h>
#include <cstdint>

// ---------------------------------------------------------------------------
// out = sx*sy * ( X@Y - zpy*rowsum(X)[m] - zpx*colsum(Y)[n] + K*zpx*zpy )
// Inputs are INT32 (harness canonical dtype), values in [-128,127].
//   d_in[0]: X [4096,4096] int32 -> packed int8 g_xp [M,K]
//   d_in[1]: Y [4096,4096] int32 -> packed+transposed int8 g_yt [N,K]
// S exact in s32 via mma.sync m16n8k32 (IMMA); fragments via ldmatrix.x4
// (mapping proven output-identical to scalar-LDS and dp4a variants).
// ---------------------------------------------------------------------------

static constexpr int MD = 4096, KD = 4096, ND = 4096;
static constexpr float KZZf = -1843200.0f;     // K*zpx*zpy = 4096*(-25)*18
static constexpr float SXY  = 0.0215f * 0.0176f;

__device__ int8_t g_xp[(size_t)MD * KD];       // 16MB packed X
__device__ int8_t g_yt[(size_t)ND * KD];       // 16MB packed transposed Y
__device__ float  g_rxf[MD];                   // -18 * rowsum_x[m]
__device__ float  g_cyf[ND];                   // +25 * colsum_y[n] + KZZ

// ------------------------------ helpers -----------------------------------

__device__ __forceinline__ uint32_t smem_u32(const void* p) {
    uint32_t a;
    asm("{ .reg .u64 t; cvta.to.shared.u64 t, %1; cvt.u32.u64 %0, t; }"
        : "=r"(a) : "l"(p));
    return a;
}

__device__ __forceinline__ void cp16(uint32_t dst, const void* src) {
    asm volatile("cp.async.cg.shared.global [%0], [%1], 16;" :: "r"(dst), "l"(src));
}
#define CP_COMMIT() asm volatile("cp.async.commit_group;" ::: "memory")

#define LDSM4(r0, r1, r2, r3, addr) \
    asm volatile("ldmatrix.sync.aligned.m8n8.x4.shared.b16 {%0,%1,%2,%3}, [%4];" \
                 : "=r"(r0), "=r"(r1), "=r"(r2), "=r"(r3) : "r"(addr))

#define MMA_S8(d, a0, a1, a2, a3, b0, b1) \
    asm volatile("mma.sync.aligned.m16n8k32.row.col.s32.s8.s8.s32 " \
                 "{%0,%1,%2,%3},{%4,%5,%6,%7},{%8,%9},{%0,%1,%2,%3};" \
                 : "+r"((d)[0]), "+r"((d)[1]), "+r"((d)[2]), "+r"((d)[3]) \
                 : "r"(a0), "r"(a1), "r"(a2), "r"(a3), "r"(b0), "r"(b1))

// smem tile layout: 128 rows x 64B, XOR-swizzled over 128B lines (8x16B slots)
__device__ __forceinline__ uint32_t sw_off(int r, int c) {
    int line = r >> 1;
    int slot = (((r & 1) * 4 + c) ^ (line & 7));
    return (uint32_t)(line * 128 + slot * 16);
}

// ------------------------------ prepasses ---------------------------------

__global__ void k_pack_x(const int4* __restrict__ q) {
    size_t i = (size_t)blockIdx.x * 256 + threadIdx.x;
    int4 v = q[i];
    char4 c;
    c.x = (char)v.x; c.y = (char)v.y; c.z = (char)v.z; c.w = (char)v.w;
    ((char4*)g_xp)[i] = c;
}

// Y int32 [K,N] -> g_yt int8 [N,K], 32x32 tiles
__global__ void k_pack_transpose_y(const int* __restrict__ Y) {
    __shared__ int8_t tile[32][36];
    int n0 = blockIdx.x * 32, k0 = blockIdx.y * 32;
    int t = threadIdx.x;
    {
        int k = t >> 3, nq = (t & 7) * 4;
        int4 v = *(const int4*)(Y + (size_t)(k0 + k) * ND + n0 + nq);
        tile[nq + 0][k] = (int8_t)v.x;
        tile[nq + 1][k] = (int8_t)v.y;
        tile[nq + 2][k] = (int8_t)v.z;
        tile[nq + 3][k] = (int8_t)v.w;
    }
    __syncthreads();
    {
        int n = t >> 3, kq = (t & 7) * 4;
        char4 c;
        c.x = tile[n][kq + 0]; c.y = tile[n][kq + 1];
        c.z = tile[n][kq + 2]; c.w = tile[n][kq + 3];
        *(char4*)(g_yt + (size_t)(n0 + n) * KD + k0 + kq) = c;
    }
}

__global__ void k_rowsum(void) {
    const unsigned* xw = (const unsigned*)g_xp;
    int m = blockIdx.x, t = threadIdx.x;
    int acc = 0;
#pragma unroll
    for (int j = 0; j < 8; j++)
        acc = __dp4a((int)xw[(size_t)m * 1024 + t + 128 * j], 0x01010101, acc);
#pragma unroll
    for (int s = 16; s; s >>= 1) acc += __shfl_xor_sync(0xffffffffu, acc, s);
    __shared__ int ws[4];
    if ((t & 31) == 0) ws[t >> 5] = acc;
    __syncthreads();
    if (t == 0) g_rxf[m] = -18.0f * (float)(ws[0] + ws[1] + ws[2] + ws[3]);
}

__global__ void k_colsum(void) {
    const unsigned* yw = (const unsigned*)g_yt;
    int n = blockIdx.x, t = threadIdx.x;
    int acc = 0;
#pragma unroll
    for (int j = 0; j < 8; j++)
        acc = __dp4a((int)yw[(size_t)n * 1024 + t + 128 * j], 0x01010101, acc);
#pragma unroll
    for (int s = 16; s; s >>= 1) acc += __shfl_xor_sync(0xffffffffu, acc, s);
    __shared__ int ws[4];
    if ((t & 31) == 0) ws[t >> 5] = acc;
    __syncthreads();
    if (t == 0) g_cyf[n] = 25.0f * (float)(ws[0] + ws[1] + ws[2] + ws[3]) + KZZf;
}

// ------------------------------- GEMM -------------------------------------
// CTA tile 128(M)x128(N), K-stage 64, 4-stage cp.async.
// 256 threads = 8 warps (4 M x 2 N), warp tile 32x64.
// Inner loop: 12 ldmatrix.x4 front-batched, then 32 IMMA.

static constexpr int STAGES = 4;
static constexpr int STAGE_BYTES = 16384;
static constexpr int SMEM_TOTAL = STAGES * STAGE_BYTES;   // 65536
static constexpr int KITERS = KD / 64;                    // 64

__device__ __forceinline__ void load_tile(uint32_t sbase, int stage, int kt,
                                          int m0, int n0) {
    const int t = threadIdx.x;
    const uint32_t sA = sbase + stage * STAGE_BYTES;
    const uint32_t sB = sA + 8192;
    const int kb = kt * 64;
#pragma unroll
    for (int j = 0; j < 2; j++) {
        int idx = t + 256 * j;              // 0..511
        int r = idx >> 2, c = idx & 3;
        cp16(sA + sw_off(r, c), g_xp + (size_t)(m0 + r) * KD + kb + c * 16);
        cp16(sB + sw_off(r, c), g_yt + (size_t)(n0 + r) * KD + kb + c * 16);
    }
}

__global__ void __launch_bounds__(256)
gemm_i8_kernel(float* __restrict__ OUT) {
    extern __shared__ char smem[];
    const uint32_t sbase = smem_u32(smem);
    const int tid = threadIdx.x;
    const int lane = tid & 31;
    const int wid = tid >> 5;
    const int wm = wid & 3;                 // M quadrant (32 rows)
    const int wn = wid >> 2;                // N half (64 cols)
    const int m0 = blockIdx.y * 128;
    const int n0 = blockIdx.x * 128;

    const int sel = lane >> 3;              // ldmatrix matrix id (0..3)
    const int l7  = lane & 7;

    int acc[2][8][4];
#pragma unroll
    for (int i = 0; i < 2; i++)
#pragma unroll
        for (int j = 0; j < 8; j++)
#pragma unroll
            for (int q = 0; q < 4; q++) acc[i][j][q] = 0;

    // prologue: 3 stages in flight
#pragma unroll
    for (int p = 0; p < 3; p++) { load_tile(sbase, p, p, m0, n0); CP_COMMIT(); }

    for (int it = 0; it < KITERS; it++) {
        asm volatile("cp.async.wait_group 2;" ::: "memory");
        __syncthreads();

        if (it + 3 < KITERS) load_tile(sbase, (it + 3) & 3, it + 3, m0, n0);
        CP_COMMIT();

        const uint32_t sA = sbase + (it & 3) * STAGE_BYTES;
        const uint32_t sB = sA + 8192;

        // ---- front-batched fragment loads: 12 LDSM4 (max MLP) ----
        uint32_t a[2][2][4];       // [ks][mt][reg]
        uint32_t b[2][4][4];       // [ks][p][reg]
#pragma unroll
        for (int ks = 0; ks < 2; ks++)
#pragma unroll
            for (int mt = 0; mt < 2; mt++) {
                int row = wm * 32 + mt * 16 + l7 + (sel & 1) * 8;
                int ch  = 2 * ks + (sel >> 1);
                LDSM4(a[ks][mt][0], a[ks][mt][1], a[ks][mt][2], a[ks][mt][3],
                      sA + sw_off(row, ch));
            }
#pragma unroll
        for (int ks = 0; ks < 2; ks++)
#pragma unroll
            for (int p = 0; p < 4; p++) {
                int nt  = p * 2 + (sel >> 1);
                int row = wn * 64 + nt * 8 + l7;
                int ch  = 2 * ks + (sel & 1);
                LDSM4(b[ks][p][0], b[ks][p][1], b[ks][p][2], b[ks][p][3],
                      sB + sw_off(row, ch));
            }

        // ---- 32 IMMA ----
#pragma unroll
        for (int ks = 0; ks < 2; ks++)
#pragma unroll
            for (int p = 0; p < 4; p++) {
                MMA_S8(acc[0][p * 2 + 0], a[ks][0][0], a[ks][0][1], a[ks][0][2], a[ks][0][3],
                       b[ks][p][0], b[ks][p][1]);
                MMA_S8(acc[0][p * 2 + 1], a[ks][0][0], a[ks][0][1], a[ks][0][2], a[ks][0][3],
                       b[ks][p][2], b[ks][p][3]);
                MMA_S8(acc[1][p * 2 + 0], a[ks][1][0], a[ks][1][1], a[ks][1][2], a[ks][1][3],
                       b[ks][p][0], b[ks][p][1]);
                MMA_S8(acc[1][p * 2 + 1], a[ks][1][0], a[ks][1][1], a[ks][1][2], a[ks][1][3],
                       b[ks][p][2], b[ks][p][3]);
            }
    }

    __syncthreads();

    // stage per-column correction into smem
    float* scy = (float*)smem;
    if (tid < 128) scy[tid] = g_cyf[n0 + tid];
    __syncthreads();

    const int gid = lane >> 2, tig = lane & 3;
#pragma unroll
    for (int mt = 0; mt < 2; mt++) {
#pragma unroll
        for (int h = 0; h < 2; h++) {
            const int rloc = wm * 32 + mt * 16 + h * 8 + gid;
            const float rf = g_rxf[m0 + rloc];
            float* orow = OUT + (size_t)(m0 + rloc) * ND + n0 + wn * 64 + tig * 2;
#pragma unroll
            for (int nt = 0; nt < 8; nt++) {
                const int cidx = wn * 64 + nt * 8 + tig * 2;
                float2 v;
                v.x = SXY * ((float)acc[mt][nt][h * 2 + 0] + rf + scy[cidx + 0]);
                v.y = SXY * ((float)acc[mt][nt][h * 2 + 1] + rf + scy[cidx + 1]);
                *(float2*)(orow + nt * 8) = v;
            }
        }
    }
}

// ------------------------------- launch ------------------------------------

extern "C" void kernel_launch(void* const* d_in, const int* in_sizes, int n_in,
                              void* d_out, int out_size) {
    const int* X32 = (const int*)d_in[0];
    const int* Y32 = (const int*)d_in[1];
    float* OUT = (float*)d_out;

    cudaFuncSetAttribute(gemm_i8_kernel,
                         cudaFuncAttributeMaxDynamicSharedMemorySize, SMEM_TOTAL);

    k_pack_x<<<16384, 256>>>((const int4*)X32);
    k_pack_transpose_y<<<dim3(ND / 32, KD / 32), 256>>>(Y32);
    k_rowsum<<<MD, 128>>>();
    k_colsum<<<ND, 128>>>();
    gemm_i8_kernel<<<dim3(ND / 128, MD / 128), 256, SMEM_TOTAL>>>(OUT);
}